// round 2
// baseline (speedup 1.0000x reference)
#include <cuda_runtime.h>
#include <cstdint>

// Problem constants (from reference)
#define N_SRC   200000
#define D       128
#define N_RULES 250000
#define PERIOD  8

// One warp per rule. D=128 f32 = 32 lanes x float4.
__global__ void __launch_bounds__(256, 8)
weighted_rule_kernel(const float* __restrict__ layer_values,
                     const float* __restrict__ weights,
                     const int* __restrict__ indices,   // JAX demotes int64->int32
                     float* __restrict__ out)
{
    const int warp_global = (blockIdx.x * blockDim.x + threadIdx.x) >> 5;
    const int lane = threadIdx.x & 31;
    if (warp_global >= N_RULES) return;

    // Lanes 0..7 load the 8 indices for this rule; broadcast via shfl.
    int my_idx = 0;
    if (lane < PERIOD) {
        my_idx = __ldg(indices + (size_t)warp_global * PERIOD + lane);
    }

    const float4* __restrict__ wbase =
        (const float4*)(weights + (size_t)warp_global * PERIOD * D);

    float4 acc = make_float4(0.f, 0.f, 0.f, 0.f);

#pragma unroll
    for (int p = 0; p < PERIOD; ++p) {
        int src = __shfl_sync(0xFFFFFFFFu, my_idx, p);
        float4 g = __ldg(((const float4*)(layer_values + (size_t)src * D)) + lane);
        float4 w = __ldg(wbase + p * (D / 4) + lane);
        acc.x = fmaf(g.x, w.x, acc.x);
        acc.y = fmaf(g.y, w.y, acc.y);
        acc.z = fmaf(g.z, w.z, acc.z);
        acc.w = fmaf(g.w, w.w, acc.w);
    }

    float4 r;
    r.x = tanhf(acc.x);
    r.y = tanhf(acc.y);
    r.z = tanhf(acc.z);
    r.w = tanhf(acc.w);

    ((float4*)(out + (size_t)warp_global * D))[lane] = r;
}

extern "C" void kernel_launch(void* const* d_in, const int* in_sizes, int n_in,
                              void* d_out, int out_size)
{
    const float* layer_values = (const float*)d_in[0];
    const float* weights      = (const float*)d_in[1];
    const int*   indices      = (const int*)d_in[2];
    float*       out          = (float*)d_out;

    const int threads = 256;                 // 8 warps = 8 rules per block
    const int rules_per_block = threads / 32;
    const int blocks = (N_RULES + rules_per_block - 1) / rules_per_block;

    weighted_rule_kernel<<<blocks, threads>>>(layer_values, weights, indices, out);
}

// round 5
// speedup vs baseline: 1.1593x; 1.1593x over previous
#include <cuda_runtime.h>
#include <cstdint>

// Problem constants (from reference)
#define N_SRC   200000
#define D       128
#define N_RULES 250000
#define PERIOD  8

// Gather load: non-coherent + L2 evict_last hint (pin layer_values in L2).
__device__ __forceinline__ float4 ld_gather(const float4* p, uint64_t pol)
{
    float4 v;
    asm volatile("ld.global.nc.L2::cache_hint.v4.f32 {%0,%1,%2,%3}, [%4], %5;"
                 : "=f"(v.x), "=f"(v.y), "=f"(v.z), "=f"(v.w)
                 : "l"(p), "l"(pol));
    return v;
}

// Streaming load for weights: evict-first, don't pollute L2.
__device__ __forceinline__ float4 ld_stream(const float4* p)
{
    float4 v;
    asm volatile("ld.global.cs.v4.f32 {%0,%1,%2,%3}, [%4];"
                 : "=f"(v.x), "=f"(v.y), "=f"(v.z), "=f"(v.w)
                 : "l"(p));
    return v;
}

// Streaming store for out.
__device__ __forceinline__ void st_stream(float4* p, float4 v)
{
    asm volatile("st.global.cs.v4.f32 [%0], {%1,%2,%3,%4};"
                 :: "l"(p), "f"(v.x), "f"(v.y), "f"(v.z), "f"(v.w)
                 : "memory");
}

// One warp per rule. D=128 f32 = 32 lanes x float4.
__global__ void __launch_bounds__(256, 8)
weighted_rule_kernel(const float* __restrict__ layer_values,
                     const float* __restrict__ weights,
                     const int* __restrict__ indices,
                     float* __restrict__ out)
{
    const int warp_global = (blockIdx.x * blockDim.x + threadIdx.x) >> 5;
    const int lane = threadIdx.x & 31;
    if (warp_global >= N_RULES) return;

    // L2 evict_last policy for the gather table (fraction 1.0).
    uint64_t pol;
    asm volatile("createpolicy.fractional.L2::evict_last.b64 %0, 1.0;" : "=l"(pol));

    // Lanes 0..7 load the 8 indices for this rule; broadcast via shfl.
    int my_idx = 0;
    if (lane < PERIOD) {
        my_idx = __ldg(indices + (size_t)warp_global * PERIOD + lane);
    }

    const float4* __restrict__ wbase =
        (const float4*)(weights + (size_t)warp_global * PERIOD * D);

    float4 acc = make_float4(0.f, 0.f, 0.f, 0.f);

#pragma unroll
    for (int p = 0; p < PERIOD; ++p) {
        int src = __shfl_sync(0xFFFFFFFFu, my_idx, p);
        float4 g = ld_gather(((const float4*)(layer_values + (size_t)src * D)) + lane, pol);
        float4 w = ld_stream(wbase + p * (D / 4) + lane);
        acc.x = fmaf(g.x, w.x, acc.x);
        acc.y = fmaf(g.y, w.y, acc.y);
        acc.z = fmaf(g.z, w.z, acc.z);
        acc.w = fmaf(g.w, w.w, acc.w);
    }

    float4 r;
    r.x = tanhf(acc.x);
    r.y = tanhf(acc.y);
    r.z = tanhf(acc.z);
    r.w = tanhf(acc.w);

    st_stream(((float4*)(out + (size_t)warp_global * D)) + lane, r);
}

extern "C" void kernel_launch(void* const* d_in, const int* in_sizes, int n_in,
                              void* d_out, int out_size)
{
    const float* layer_values = (const float*)d_in[0];
    const float* weights      = (const float*)d_in[1];
    const int*   indices      = (const int*)d_in[2];
    float*       out          = (float*)d_out;

    const int threads = 256;                 // 8 warps = 8 rules per block
    const int rules_per_block = threads / 32;
    const int blocks = (N_RULES + rules_per_block - 1) / rules_per_block;

    weighted_rule_kernel<<<blocks, threads>>>(layer_values, weights, indices, out);
}

// round 6
// speedup vs baseline: 1.1693x; 1.0087x over previous
#include <cuda_runtime.h>
#include <cstdint>

// Problem constants (from reference)
#define N_SRC   200000
#define D       128
#define N_RULES 250000
#define PERIOD  8

// Gather load: non-coherent + L2 evict_last hint (pin layer_values in L2).
__device__ __forceinline__ float4 ld_gather(const float4* p, uint64_t pol)
{
    float4 v;
    asm volatile("ld.global.nc.L2::cache_hint.v4.f32 {%0,%1,%2,%3}, [%4], %5;"
                 : "=f"(v.x), "=f"(v.y), "=f"(v.z), "=f"(v.w)
                 : "l"(p), "l"(pol));
    return v;
}

// Streaming load for weights: explicit evict_first policy + 256B L2 prefetch.
__device__ __forceinline__ float4 ld_stream(const float4* p, uint64_t pol)
{
    float4 v;
    asm volatile("ld.global.nc.L2::cache_hint.L2::256B.v4.f32 {%0,%1,%2,%3}, [%4], %5;"
                 : "=f"(v.x), "=f"(v.y), "=f"(v.z), "=f"(v.w)
                 : "l"(p), "l"(pol));
    return v;
}

// Streaming store for out (evict-first).
__device__ __forceinline__ void st_stream(float4* p, float4 v)
{
    asm volatile("st.global.cs.v4.f32 [%0], {%1,%2,%3,%4};"
                 :: "l"(p), "f"(v.x), "f"(v.y), "f"(v.z), "f"(v.w)
                 : "memory");
}

// One warp per TWO rules (doubles memory-level parallelism).
// D=128 f32 = 32 lanes x float4 per rule row.
__global__ void __launch_bounds__(256)
weighted_rule_kernel(const float* __restrict__ layer_values,
                     const float* __restrict__ weights,
                     const int* __restrict__ indices,
                     float* __restrict__ out)
{
    const int warp_global = (blockIdx.x * blockDim.x + threadIdx.x) >> 5;
    const int lane = threadIdx.x & 31;
    const int rule0 = warp_global * 2;
    if (rule0 >= N_RULES) return;

    // Policies: pin gather table (evict_last), demote weight stream (evict_first).
    uint64_t pol_keep, pol_stream;
    asm volatile("createpolicy.fractional.L2::evict_last.b64 %0, 1.0;"  : "=l"(pol_keep));
    asm volatile("createpolicy.fractional.L2::evict_first.b64 %0, 1.0;" : "=l"(pol_stream));

    // Lanes 0..7 hold indices of rule0, lanes 8..15 hold indices of rule1.
    int my_idx = 0;
    if (lane < 2 * PERIOD) {
        my_idx = __ldg(indices + (size_t)rule0 * PERIOD + lane);
    }

    const float4* __restrict__ wbase =
        (const float4*)(weights + (size_t)rule0 * PERIOD * D);

    float4 acc0 = make_float4(0.f, 0.f, 0.f, 0.f);
    float4 acc1 = make_float4(0.f, 0.f, 0.f, 0.f);

#pragma unroll
    for (int p = 0; p < PERIOD; ++p) {
        int src0 = __shfl_sync(0xFFFFFFFFu, my_idx, p);
        int src1 = __shfl_sync(0xFFFFFFFFu, my_idx, PERIOD + p);
        float4 g0 = ld_gather(((const float4*)(layer_values + (size_t)src0 * D)) + lane, pol_keep);
        float4 g1 = ld_gather(((const float4*)(layer_values + (size_t)src1 * D)) + lane, pol_keep);
        float4 w0 = ld_stream(wbase + p * (D / 4) + lane, pol_stream);
        float4 w1 = ld_stream(wbase + (PERIOD + p) * (D / 4) + lane, pol_stream);
        acc0.x = fmaf(g0.x, w0.x, acc0.x);
        acc0.y = fmaf(g0.y, w0.y, acc0.y);
        acc0.z = fmaf(g0.z, w0.z, acc0.z);
        acc0.w = fmaf(g0.w, w0.w, acc0.w);
        acc1.x = fmaf(g1.x, w1.x, acc1.x);
        acc1.y = fmaf(g1.y, w1.y, acc1.y);
        acc1.z = fmaf(g1.z, w1.z, acc1.z);
        acc1.w = fmaf(g1.w, w1.w, acc1.w);
    }

    float4 r0, r1;
    r0.x = tanhf(acc0.x); r0.y = tanhf(acc0.y);
    r0.z = tanhf(acc0.z); r0.w = tanhf(acc0.w);
    r1.x = tanhf(acc1.x); r1.y = tanhf(acc1.y);
    r1.z = tanhf(acc1.z); r1.w = tanhf(acc1.w);

    st_stream(((float4*)(out + (size_t)rule0 * D)) + lane, r0);
    st_stream(((float4*)(out + (size_t)(rule0 + 1) * D)) + lane, r1);
}

extern "C" void kernel_launch(void* const* d_in, const int* in_sizes, int n_in,
                              void* d_out, int out_size)
{
    const float* layer_values = (const float*)d_in[0];
    const float* weights      = (const float*)d_in[1];
    const int*   indices      = (const int*)d_in[2];
    float*       out          = (float*)d_out;

    const int threads = 256;                     // 8 warps = 16 rules per block
    const int rules_per_block = (threads / 32) * 2;
    const int blocks = (N_RULES + rules_per_block - 1) / rules_per_block;

    weighted_rule_kernel<<<blocks, threads>>>(layer_values, weights, indices, out);
}

// round 7
// speedup vs baseline: 1.2614x; 1.0787x over previous
#include <cuda_runtime.h>
#include <cuda_fp16.h>
#include <cstdint>

// Problem constants (from reference)
#define N_SRC   200000
#define D       128
#define N_RULES 250000
#define PERIOD  8

// fp16 copy of the gather table: 200000*128*2 = 51.2 MB (fits L2 w/ slack).
__device__ __half g_lv_h[(size_t)N_SRC * D];

// ---- cache-policy memory helpers -------------------------------------------

__device__ __forceinline__ float4 ld_f4_hint(const float4* p, uint64_t pol)
{
    float4 v;
    asm volatile("ld.global.nc.L2::cache_hint.v4.f32 {%0,%1,%2,%3}, [%4], %5;"
                 : "=f"(v.x), "=f"(v.y), "=f"(v.z), "=f"(v.w)
                 : "l"(p), "l"(pol));
    return v;
}

__device__ __forceinline__ void ld_u2_hint(const void* p, uint64_t pol,
                                           unsigned& a, unsigned& b)
{
    asm volatile("ld.global.nc.L2::cache_hint.v2.b32 {%0,%1}, [%2], %3;"
                 : "=r"(a), "=r"(b)
                 : "l"(p), "l"(pol));
}

__device__ __forceinline__ void st_u2_hint(void* p, unsigned a, unsigned b,
                                           uint64_t pol)
{
    asm volatile("st.global.L2::cache_hint.v2.b32 [%0], {%1,%2}, %3;"
                 :: "l"(p), "r"(a), "r"(b), "l"(pol)
                 : "memory");
}

__device__ __forceinline__ void st_stream_f4(float4* p, float4 v)
{
    asm volatile("st.global.cs.v4.f32 [%0], {%1,%2,%3,%4};"
                 :: "l"(p), "f"(v.x), "f"(v.y), "f"(v.z), "f"(v.w)
                 : "memory");
}

// ---- kernel 1: f32 -> fp16 table conversion --------------------------------
// Reads layer_values with evict_first (don't pollute L2 with the f32 copy),
// writes the fp16 table with evict_last (pre-warm + pin in L2).
__global__ void __launch_bounds__(256)
convert_table_kernel(const float* __restrict__ layer_values)
{
    uint64_t pol_keep, pol_stream;
    asm volatile("createpolicy.fractional.L2::evict_last.b64 %0, 1.0;"  : "=l"(pol_keep));
    asm volatile("createpolicy.fractional.L2::evict_first.b64 %0, 1.0;" : "=l"(pol_stream));

    const size_t i = (size_t)blockIdx.x * blockDim.x + threadIdx.x;  // float4 index
    const size_t total4 = (size_t)N_SRC * D / 4;
    if (i >= total4) return;

    float4 v = ld_f4_hint((const float4*)layer_values + i, pol_stream);
    __half2 h01 = __floats2half2_rn(v.x, v.y);
    __half2 h23 = __floats2half2_rn(v.z, v.w);
    unsigned lo = *reinterpret_cast<unsigned*>(&h01);
    unsigned hi = *reinterpret_cast<unsigned*>(&h23);
    st_u2_hint((char*)g_lv_h + i * 8, lo, hi, pol_keep);
}

// ---- kernel 2: main weighted-rule kernel -----------------------------------
// One warp per TWO rules. Gather rows are fp16 (256 B/row = 32 lanes x 8 B).
__global__ void __launch_bounds__(256)
weighted_rule_kernel(const float* __restrict__ weights,
                     const int* __restrict__ indices,
                     float* __restrict__ out)
{
    const int warp_global = (blockIdx.x * blockDim.x + threadIdx.x) >> 5;
    const int lane = threadIdx.x & 31;
    const int rule0 = warp_global * 2;
    if (rule0 >= N_RULES) return;

    uint64_t pol_keep, pol_stream;
    asm volatile("createpolicy.fractional.L2::evict_last.b64 %0, 1.0;"  : "=l"(pol_keep));
    asm volatile("createpolicy.fractional.L2::evict_first.b64 %0, 1.0;" : "=l"(pol_stream));

    // Lanes 0..7: indices of rule0, lanes 8..15: indices of rule1.
    int my_idx = 0;
    if (lane < 2 * PERIOD) {
        my_idx = __ldg(indices + (size_t)rule0 * PERIOD + lane);
    }

    const float4* __restrict__ wbase =
        (const float4*)(weights + (size_t)rule0 * PERIOD * D);

    float4 acc0 = make_float4(0.f, 0.f, 0.f, 0.f);
    float4 acc1 = make_float4(0.f, 0.f, 0.f, 0.f);

#pragma unroll
    for (int p = 0; p < PERIOD; ++p) {
        int src0 = __shfl_sync(0xFFFFFFFFu, my_idx, p);
        int src1 = __shfl_sync(0xFFFFFFFFu, my_idx, PERIOD + p);

        // fp16 gather: lane owns columns [4*lane, 4*lane+4) -> 8 bytes.
        unsigned a0, b0, a1, b1;
        ld_u2_hint((const char*)g_lv_h + ((size_t)src0 * D + lane * 4) * 2, pol_keep, a0, b0);
        ld_u2_hint((const char*)g_lv_h + ((size_t)src1 * D + lane * 4) * 2, pol_keep, a1, b1);

        float4 w0 = ld_f4_hint(wbase + p * (D / 4) + lane, pol_stream);
        float4 w1 = ld_f4_hint(wbase + (PERIOD + p) * (D / 4) + lane, pol_stream);

        __half2 h;
        *reinterpret_cast<unsigned*>(&h) = a0;
        float2 f01 = __half22float2(h);
        *reinterpret_cast<unsigned*>(&h) = b0;
        float2 f23 = __half22float2(h);
        acc0.x = fmaf(f01.x, w0.x, acc0.x);
        acc0.y = fmaf(f01.y, w0.y, acc0.y);
        acc0.z = fmaf(f23.x, w0.z, acc0.z);
        acc0.w = fmaf(f23.y, w0.w, acc0.w);

        *reinterpret_cast<unsigned*>(&h) = a1;
        f01 = __half22float2(h);
        *reinterpret_cast<unsigned*>(&h) = b1;
        f23 = __half22float2(h);
        acc1.x = fmaf(f01.x, w1.x, acc1.x);
        acc1.y = fmaf(f01.y, w1.y, acc1.y);
        acc1.z = fmaf(f23.x, w1.z, acc1.z);
        acc1.w = fmaf(f23.y, w1.w, acc1.w);
    }

    float4 r0, r1;
    r0.x = tanhf(acc0.x); r0.y = tanhf(acc0.y);
    r0.z = tanhf(acc0.z); r0.w = tanhf(acc0.w);
    r1.x = tanhf(acc1.x); r1.y = tanhf(acc1.y);
    r1.z = tanhf(acc1.z); r1.w = tanhf(acc1.w);

    st_stream_f4(((float4*)(out + (size_t)rule0 * D)) + lane, r0);
    st_stream_f4(((float4*)(out + (size_t)(rule0 + 1) * D)) + lane, r1);
}

extern "C" void kernel_launch(void* const* d_in, const int* in_sizes, int n_in,
                              void* d_out, int out_size)
{
    const float* layer_values = (const float*)d_in[0];
    const float* weights      = (const float*)d_in[1];
    const int*   indices      = (const int*)d_in[2];
    float*       out          = (float*)d_out;

    // Kernel 1: build fp16 table (6.4M float4 elements).
    {
        const int threads = 256;
        const int total4  = N_SRC * D / 4;            // 6,400,000
        const int blocks  = (total4 + threads - 1) / threads;
        convert_table_kernel<<<blocks, threads>>>(layer_values);
    }

    // Kernel 2: main compute.
    {
        const int threads = 256;                      // 8 warps = 16 rules/block
        const int rules_per_block = (threads / 32) * 2;
        const int blocks = (N_RULES + rules_per_block - 1) / rules_per_block;
        weighted_rule_kernel<<<blocks, threads>>>(weights, indices, out);
    }
}

// round 9
// speedup vs baseline: 1.2727x; 1.0090x over previous
#include <cuda_runtime.h>
#include <cuda_fp16.h>
#include <cstdint>

// Problem constants (from reference)
#define N_SRC   200000
#define D       128
#define N_RULES 250000
#define PERIOD  8

// fp16 copy of the gather table: 200000*128*2 = 51.2 MB (fits L2 w/ slack).
__device__ __half g_lv_h[(size_t)N_SRC * D];

// ---- cache-policy memory helpers -------------------------------------------

__device__ __forceinline__ float4 ld_f4_hint(const float4* p, uint64_t pol)
{
    float4 v;
    asm volatile("ld.global.nc.L2::cache_hint.v4.f32 {%0,%1,%2,%3}, [%4], %5;"
                 : "=f"(v.x), "=f"(v.y), "=f"(v.z), "=f"(v.w)
                 : "l"(p), "l"(pol));
    return v;
}

// Weight-stream load: evict_first + 256B L2 prefetch (sequential stream).
__device__ __forceinline__ float4 ld_f4_stream(const float4* p, uint64_t pol)
{
    float4 v;
    asm volatile("ld.global.nc.L2::cache_hint.L2::256B.v4.f32 {%0,%1,%2,%3}, [%4], %5;"
                 : "=f"(v.x), "=f"(v.y), "=f"(v.z), "=f"(v.w)
                 : "l"(p), "l"(pol));
    return v;
}

__device__ __forceinline__ void ld_u2_hint(const void* p, uint64_t pol,
                                           unsigned& a, unsigned& b)
{
    asm volatile("ld.global.nc.L2::cache_hint.v2.b32 {%0,%1}, [%2], %3;"
                 : "=r"(a), "=r"(b)
                 : "l"(p), "l"(pol));
}

__device__ __forceinline__ void st_u4_hint(void* p, unsigned a, unsigned b,
                                           unsigned c, unsigned d, uint64_t pol)
{
    asm volatile("st.global.L2::cache_hint.v4.b32 [%0], {%1,%2,%3,%4}, %5;"
                 :: "l"(p), "r"(a), "r"(b), "r"(c), "r"(d), "l"(pol)
                 : "memory");
}

__device__ __forceinline__ void st_stream_f4(float4* p, float4 v)
{
    asm volatile("st.global.cs.v4.f32 [%0], {%1,%2,%3,%4};"
                 :: "l"(p), "f"(v.x), "f"(v.y), "f"(v.z), "f"(v.w)
                 : "memory");
}

// ---- kernel 1: f32 -> fp16 table conversion --------------------------------
// Each thread: read 2 x float4 (32 B, evict_first + 256B prefetch),
// write 1 x 16 B fp16 (evict_last: pre-warm + pin the table in L2).
__global__ void __launch_bounds__(256)
convert_table_kernel(const float* __restrict__ layer_values)
{
    uint64_t pol_keep, pol_stream;
    asm volatile("createpolicy.fractional.L2::evict_last.b64 %0, 1.0;"  : "=l"(pol_keep));
    asm volatile("createpolicy.fractional.L2::evict_first.b64 %0, 1.0;" : "=l"(pol_stream));

    const size_t i = (size_t)blockIdx.x * blockDim.x + threadIdx.x;  // 8-float chunk idx
    const size_t total8 = (size_t)N_SRC * D / 8;                     // 3,200,000
    if (i >= total8) return;

    const float4* src = (const float4*)layer_values + i * 2;
    float4 v0 = ld_f4_stream(src,     pol_stream);
    float4 v1 = ld_f4_stream(src + 1, pol_stream);

    __half2 h0 = __floats2half2_rn(v0.x, v0.y);
    __half2 h1 = __floats2half2_rn(v0.z, v0.w);
    __half2 h2 = __floats2half2_rn(v1.x, v1.y);
    __half2 h3 = __floats2half2_rn(v1.z, v1.w);

    st_u4_hint((char*)g_lv_h + i * 16,
               *reinterpret_cast<unsigned*>(&h0),
               *reinterpret_cast<unsigned*>(&h1),
               *reinterpret_cast<unsigned*>(&h2),
               *reinterpret_cast<unsigned*>(&h3), pol_keep);
}

// ---- kernel 2: main weighted-rule kernel -----------------------------------
// One warp per TWO rules. Gather rows are fp16 (256 B/row = 32 lanes x 8 B).
__global__ void __launch_bounds__(256)
weighted_rule_kernel(const float* __restrict__ weights,
                     const int* __restrict__ indices,
                     float* __restrict__ out)
{
    const int warp_global = (blockIdx.x * blockDim.x + threadIdx.x) >> 5;
    const int lane = threadIdx.x & 31;
    const int rule0 = warp_global * 2;
    if (rule0 >= N_RULES) return;

    uint64_t pol_keep, pol_stream;
    asm volatile("createpolicy.fractional.L2::evict_last.b64 %0, 1.0;"  : "=l"(pol_keep));
    asm volatile("createpolicy.fractional.L2::evict_first.b64 %0, 1.0;" : "=l"(pol_stream));

    // Lanes 0..7: indices of rule0, lanes 8..15: indices of rule1.
    int my_idx = 0;
    if (lane < 2 * PERIOD) {
        my_idx = __ldg(indices + (size_t)rule0 * PERIOD + lane);
    }

    const float4* __restrict__ wbase =
        (const float4*)(weights + (size_t)rule0 * PERIOD * D);

    float4 acc0 = make_float4(0.f, 0.f, 0.f, 0.f);
    float4 acc1 = make_float4(0.f, 0.f, 0.f, 0.f);

#pragma unroll
    for (int p = 0; p < PERIOD; ++p) {
        int src0 = __shfl_sync(0xFFFFFFFFu, my_idx, p);
        int src1 = __shfl_sync(0xFFFFFFFFu, my_idx, PERIOD + p);

        // fp16 gather: lane owns columns [4*lane, 4*lane+4) -> 8 bytes.
        unsigned a0, b0, a1, b1;
        ld_u2_hint((const char*)g_lv_h + ((size_t)src0 * D + lane * 4) * 2, pol_keep, a0, b0);
        ld_u2_hint((const char*)g_lv_h + ((size_t)src1 * D + lane * 4) * 2, pol_keep, a1, b1);

        float4 w0 = ld_f4_stream(wbase + p * (D / 4) + lane, pol_stream);
        float4 w1 = ld_f4_stream(wbase + (PERIOD + p) * (D / 4) + lane, pol_stream);

        __half2 h;
        *reinterpret_cast<unsigned*>(&h) = a0;
        float2 f01 = __half22float2(h);
        *reinterpret_cast<unsigned*>(&h) = b0;
        float2 f23 = __half22float2(h);
        acc0.x = fmaf(f01.x, w0.x, acc0.x);
        acc0.y = fmaf(f01.y, w0.y, acc0.y);
        acc0.z = fmaf(f23.x, w0.z, acc0.z);
        acc0.w = fmaf(f23.y, w0.w, acc0.w);

        *reinterpret_cast<unsigned*>(&h) = a1;
        f01 = __half22float2(h);
        *reinterpret_cast<unsigned*>(&h) = b1;
        f23 = __half22float2(h);
        acc1.x = fmaf(f01.x, w1.x, acc1.x);
        acc1.y = fmaf(f01.y, w1.y, acc1.y);
        acc1.z = fmaf(f23.x, w1.z, acc1.z);
        acc1.w = fmaf(f23.y, w1.w, acc1.w);
    }

    float4 r0, r1;
    r0.x = tanhf(acc0.x); r0.y = tanhf(acc0.y);
    r0.z = tanhf(acc0.z); r0.w = tanhf(acc0.w);
    r1.x = tanhf(acc1.x); r1.y = tanhf(acc1.y);
    r1.z = tanhf(acc1.z); r1.w = tanhf(acc1.w);

    st_stream_f4(((float4*)(out + (size_t)rule0 * D)) + lane, r0);
    st_stream_f4(((float4*)(out + (size_t)(rule0 + 1) * D)) + lane, r1);
}

extern "C" void kernel_launch(void* const* d_in, const int* in_sizes, int n_in,
                              void* d_out, int out_size)
{
    const float* layer_values = (const float*)d_in[0];
    const float* weights      = (const float*)d_in[1];
    const int*   indices      = (const int*)d_in[2];
    float*       out          = (float*)d_out;

    // Kernel 1: build fp16 table (3.2M 8-float chunks).
    {
        const int threads = 256;
        const int total8  = N_SRC * D / 8;            // 3,200,000
        const int blocks  = (total8 + threads - 1) / threads;
        convert_table_kernel<<<blocks, threads>>>(layer_values);
    }

    // Kernel 2: main compute.
    {
        const int threads = 256;                      // 8 warps = 16 rules/block
        const int rules_per_block = (threads / 32) * 2;
        const int blocks = (N_RULES + rules_per_block - 1) / rules_per_block;
        weighted_rule_kernel<<<blocks, threads>>>(weights, indices, out);
    }
}

// round 10
// speedup vs baseline: 1.3026x; 1.0235x over previous
#include <cuda_runtime.h>
#include <cuda_fp16.h>
#include <cstdint>

// Problem constants (from reference)
#define N_SRC   200000
#define D       128
#define N_RULES 250000
#define PERIOD  8

// fp16 copy of the gather table: 200000*128*2 = 51.2 MB (L2-resident w/ slack).
__device__ __half g_lv_h[(size_t)N_SRC * D];

// ---- cache-policy memory helpers -------------------------------------------

// Weight/table-source stream load: evict_first + 256B L2 prefetch.
__device__ __forceinline__ float4 ld_f4_stream(const float4* p, uint64_t pol)
{
    float4 v;
    asm volatile("ld.global.nc.L2::cache_hint.L2::256B.v4.f32 {%0,%1,%2,%3}, [%4], %5;"
                 : "=f"(v.x), "=f"(v.y), "=f"(v.z), "=f"(v.w)
                 : "l"(p), "l"(pol));
    return v;
}

// Gather load: 8 bytes, pinned in L2 via evict_last.
__device__ __forceinline__ void ld_u2_hint(const void* p, uint64_t pol,
                                           unsigned& a, unsigned& b)
{
    asm volatile("ld.global.nc.L2::cache_hint.v2.b32 {%0,%1}, [%2], %3;"
                 : "=r"(a), "=r"(b)
                 : "l"(p), "l"(pol));
}

__device__ __forceinline__ void st_u4_hint(void* p, unsigned a, unsigned b,
                                           unsigned c, unsigned d, uint64_t pol)
{
    asm volatile("st.global.L2::cache_hint.v4.b32 [%0], {%1,%2,%3,%4}, %5;"
                 :: "l"(p), "r"(a), "r"(b), "r"(c), "r"(d), "l"(pol)
                 : "memory");
}

__device__ __forceinline__ void st_stream_f4(float4* p, float4 v)
{
    asm volatile("st.global.cs.v4.f32 [%0], {%1,%2,%3,%4};"
                 :: "l"(p), "f"(v.x), "f"(v.y), "f"(v.z), "f"(v.w)
                 : "memory");
}

// ---- kernel 1: f32 -> fp16 table conversion --------------------------------
// Each thread: read 4 x float4 (64 B, evict_first + 256B prefetch),
// write 2 x 16 B fp16 (evict_last: pre-warm + pin the table in L2).
__global__ void __launch_bounds__(256)
convert_table_kernel(const float* __restrict__ layer_values)
{
    uint64_t pol_keep, pol_stream;
    asm volatile("createpolicy.fractional.L2::evict_last.b64 %0, 1.0;"  : "=l"(pol_keep));
    asm volatile("createpolicy.fractional.L2::evict_first.b64 %0, 1.0;" : "=l"(pol_stream));

    const size_t i = (size_t)blockIdx.x * blockDim.x + threadIdx.x;  // 16-float chunk
    const size_t total16 = (size_t)N_SRC * D / 16;                   // 1,600,000
    if (i >= total16) return;

    const float4* src = (const float4*)layer_values + i * 4;
    float4 v0 = ld_f4_stream(src,     pol_stream);
    float4 v1 = ld_f4_stream(src + 1, pol_stream);
    float4 v2 = ld_f4_stream(src + 2, pol_stream);
    float4 v3 = ld_f4_stream(src + 3, pol_stream);

    __half2 h0 = __floats2half2_rn(v0.x, v0.y);
    __half2 h1 = __floats2half2_rn(v0.z, v0.w);
    __half2 h2 = __floats2half2_rn(v1.x, v1.y);
    __half2 h3 = __floats2half2_rn(v1.z, v1.w);
    __half2 h4 = __floats2half2_rn(v2.x, v2.y);
    __half2 h5 = __floats2half2_rn(v2.z, v2.w);
    __half2 h6 = __floats2half2_rn(v3.x, v3.y);
    __half2 h7 = __floats2half2_rn(v3.z, v3.w);

    char* dst = (char*)g_lv_h + i * 32;
    st_u4_hint(dst,
               *reinterpret_cast<unsigned*>(&h0),
               *reinterpret_cast<unsigned*>(&h1),
               *reinterpret_cast<unsigned*>(&h2),
               *reinterpret_cast<unsigned*>(&h3), pol_keep);
    st_u4_hint(dst + 16,
               *reinterpret_cast<unsigned*>(&h4),
               *reinterpret_cast<unsigned*>(&h5),
               *reinterpret_cast<unsigned*>(&h6),
               *reinterpret_cast<unsigned*>(&h7), pol_keep);
}

// ---- kernel 2: main weighted-rule kernel -----------------------------------
// One warp per rule (best measured DRAM saturation shape).
// Gather rows are fp16 (256 B/row = 32 lanes x 8 B); weights f32 float4/lane.
__global__ void __launch_bounds__(256, 8)
weighted_rule_kernel(const float* __restrict__ weights,
                     const int* __restrict__ indices,
                     float* __restrict__ out)
{
    const int warp_global = (blockIdx.x * blockDim.x + threadIdx.x) >> 5;
    const int lane = threadIdx.x & 31;
    if (warp_global >= N_RULES) return;

    uint64_t pol_keep, pol_stream;
    asm volatile("createpolicy.fractional.L2::evict_last.b64 %0, 1.0;"  : "=l"(pol_keep));
    asm volatile("createpolicy.fractional.L2::evict_first.b64 %0, 1.0;" : "=l"(pol_stream));

    // Lanes 0..7 load the 8 indices for this rule; broadcast via shfl.
    int my_idx = 0;
    if (lane < PERIOD) {
        my_idx = __ldg(indices + (size_t)warp_global * PERIOD + lane);
    }

    const float4* __restrict__ wbase =
        (const float4*)(weights + (size_t)warp_global * PERIOD * D);

    float4 acc = make_float4(0.f, 0.f, 0.f, 0.f);

#pragma unroll
    for (int p = 0; p < PERIOD; ++p) {
        int src = __shfl_sync(0xFFFFFFFFu, my_idx, p);

        // fp16 gather: lane owns columns [4*lane, 4*lane+4) -> 8 bytes.
        unsigned a, b;
        ld_u2_hint((const char*)g_lv_h + ((size_t)src * D + lane * 4) * 2, pol_keep, a, b);

        float4 w = ld_f4_stream(wbase + p * (D / 4) + lane, pol_stream);

        __half2 h;
        *reinterpret_cast<unsigned*>(&h) = a;
        float2 f01 = __half22float2(h);
        *reinterpret_cast<unsigned*>(&h) = b;
        float2 f23 = __half22float2(h);
        acc.x = fmaf(f01.x, w.x, acc.x);
        acc.y = fmaf(f01.y, w.y, acc.y);
        acc.z = fmaf(f23.x, w.z, acc.z);
        acc.w = fmaf(f23.y, w.w, acc.w);
    }

    float4 r;
    r.x = tanhf(acc.x);
    r.y = tanhf(acc.y);
    r.z = tanhf(acc.z);
    r.w = tanhf(acc.w);

    st_stream_f4(((float4*)(out + (size_t)warp_global * D)) + lane, r);
}

extern "C" void kernel_launch(void* const* d_in, const int* in_sizes, int n_in,
                              void* d_out, int out_size)
{
    const float* layer_values = (const float*)d_in[0];
    const float* weights      = (const float*)d_in[1];
    const int*   indices      = (const int*)d_in[2];
    float*       out          = (float*)d_out;

    // Kernel 1: build fp16 table (1.6M 16-float chunks).
    {
        const int threads = 256;
        const int total16 = N_SRC * D / 16;           // 1,600,000
        const int blocks  = (total16 + threads - 1) / threads;
        convert_table_kernel<<<blocks, threads>>>(layer_values);
    }

    // Kernel 2: main compute, one warp per rule.
    {
        const int threads = 256;                      // 8 warps = 8 rules/block
        const int rules_per_block = threads / 32;
        const int blocks = (N_RULES + rules_per_block - 1) / rules_per_block;
        weighted_rule_kernel<<<blocks, threads>>>(weights, indices, out);
    }
}